// round 16
// baseline (speedup 1.0000x reference)
#include <cuda_runtime.h>
#include <cuda_bf16.h>
#include <math.h>

#define T_SEQ 2048
#define BATCH 256
// lstm_rec per k-quarter (32 k): RKQ in registers, SKQ in smem
#define RKQ 24
#define SKQ 8

typedef unsigned long long u64;

// xg scratch: [B][T][4H] fp32 = 1 GiB. __device__ global (no cudaMalloc allowed).
__device__ float g_xg[268435456];
// Pre-converted Wih bf16 hi/lo, per-chunk swizzled images (8 chunks x 16 KB).
__device__ __align__(16) unsigned char g_whi[131072];
__device__ __align__(16) unsigned char g_wlo[131072];

// ---- f32x2 packed-math helpers (sm_103a FFMA2) --------------------------
__device__ __forceinline__ u64 pack2(float lo, float hi) {
    u64 r; asm("mov.b64 %0, {%1, %2};" : "=l"(r) : "f"(lo), "f"(hi)); return r;
}
__device__ __forceinline__ u64 dup2(float v) {
    u64 r; asm("mov.b64 %0, {%1, %1};" : "=l"(r) : "f"(v)); return r;
}
__device__ __forceinline__ void ffma2(u64& d, u64 a, u64 b) {
    asm("fma.rn.f32x2 %0, %1, %2, %0;" : "+l"(d) : "l"(a), "l"(b));
}
__device__ __forceinline__ u64 add2(u64 a, u64 b) {
    u64 r; asm("add.rn.f32x2 %0, %1, %2;" : "=l"(r) : "l"(a), "l"(b)); return r;
}
__device__ __forceinline__ void unpack2(u64 v, float& lo, float& hi) {
    asm("mov.b64 {%0, %1}, %2;" : "=f"(lo), "=f"(hi) : "l"(v));
}
__device__ __forceinline__ float tanhapx(float x) {
    float r; asm("tanh.approx.f32 %0, %1;" : "=f"(r) : "f"(x)); return r;
}
__device__ __forceinline__ float sigapx(float x) {
    return fmaf(0.5f, tanhapx(0.5f * x), 0.5f);
}

// ---- shared helpers -------------------------------------------------------
__device__ __forceinline__ unsigned smem_u32(const void* p) {
    unsigned a;
    asm("{ .reg .u64 t; cvta.to.shared.u64 t, %1; cvt.u32.u64 %0, t; }"
        : "=r"(a) : "l"(p));
    return a;
}
__device__ __forceinline__ void ldmatrix_x4(unsigned* r, unsigned addr) {
    asm volatile("ldmatrix.sync.aligned.m8n8.x4.shared.b16 {%0,%1,%2,%3}, [%4];"
                 : "=r"(r[0]), "=r"(r[1]), "=r"(r[2]), "=r"(r[3]) : "r"(addr));
}
__device__ __forceinline__ void ldmatrix_x2(unsigned* r, unsigned addr) {
    asm volatile("ldmatrix.sync.aligned.m8n8.x2.shared.b16 {%0,%1}, [%2];"
                 : "=r"(r[0]), "=r"(r[1]) : "r"(addr));
}
__device__ __forceinline__ void mma_bf16(float* d, const unsigned* a, const unsigned* b) {
    asm volatile(
        "mma.sync.aligned.m16n8k16.row.col.f32.bf16.bf16.f32 "
        "{%0,%1,%2,%3}, {%4,%5,%6,%7}, {%8,%9}, {%0,%1,%2,%3};"
        : "+f"(d[0]), "+f"(d[1]), "+f"(d[2]), "+f"(d[3])
        : "r"(a[0]), "r"(a[1]), "r"(a[2]), "r"(a[3]), "r"(b[0]), "r"(b[1]));
}
__device__ __forceinline__ unsigned short bfbits(__nv_bfloat16 h) {
    unsigned short s; memcpy(&s, &h, 2); return s;
}
// swizzled byte offset of 16B chunk c in row r (rows of 256B = 128 bf16)
__device__ __forceinline__ unsigned sw_off(int r, int c) {
    return (unsigned)r * 256u + (unsigned)(c ^ (r & 7)) * 16u;
}
__device__ __forceinline__ void cvt_hi_lo(float4 v, u64& hi, u64& lo) {
    __nv_bfloat16 hx = __float2bfloat16_rn(v.x);
    __nv_bfloat16 hy = __float2bfloat16_rn(v.y);
    __nv_bfloat16 hz = __float2bfloat16_rn(v.z);
    __nv_bfloat16 hw = __float2bfloat16_rn(v.w);
    hi = (u64)bfbits(hx) | ((u64)bfbits(hy) << 16)
       | ((u64)bfbits(hz) << 32) | ((u64)bfbits(hw) << 48);
    __nv_bfloat16 lx = __float2bfloat16_rn(v.x - __bfloat162float(hx));
    __nv_bfloat16 ly = __float2bfloat16_rn(v.y - __bfloat162float(hy));
    __nv_bfloat16 lz = __float2bfloat16_rn(v.z - __bfloat162float(hz));
    __nv_bfloat16 lw = __float2bfloat16_rn(v.w - __bfloat162float(hw));
    lo = (u64)bfbits(lx) | ((u64)bfbits(ly) << 16)
       | ((u64)bfbits(lz) << 32) | ((u64)bfbits(lw) << 48);
}

// ============================================================================
// Kernel W: one-shot Wih -> bf16 hi/lo in per-chunk swizzled blocked layout.
// ============================================================================
__global__ void __launch_bounds__(256, 4)
wprep(const float* __restrict__ Wih)
{
    int e = blockIdx.x * 256 + threadIdx.x;   // 0..16383
    int ch = e >> 11;
    int r  = (e >> 5) & 63;
    int f4c = e & 31;
    int g = ch * 64 + r;
    float4 v = ((const float4*)Wih)[g * 32 + f4c];
    int k = 4 * f4c;
    unsigned off = (unsigned)(ch * 16384) + sw_off(r, k >> 3) + (unsigned)(k & 7) * 2u;
    u64 hi, lo;
    cvt_hi_lo(v, hi, lo);
    *(u64*)(g_whi + off) = hi;
    *(u64*)(g_wlo + off) = lo;
}

// ============================================================================
// Kernel A: xg = x @ Wih^T + bih + bhh via mma.sync bf16-3x (R15 verbatim).
// ============================================================================

#define SM_XHI 0
#define SM_XLO 32768
#define SM_WHI 65536
#define SM_WLO 81920
#define SM_STAGE 98304            // [128][68] f32 = 34816 B
#define SM_TOTAL_A 133120

__global__ void __launch_bounds__(256, 1)
xg_mma(const float* __restrict__ x, const float* __restrict__ Wih,
       const float* __restrict__ bih, const float* __restrict__ bhh)
{
    extern __shared__ char smc[];
    float* STG = (float*)(smc + SM_STAGE);
    const unsigned smem_base = smem_u32(smc);
    const unsigned XHIb = smem_base + SM_XHI, XLOb = smem_base + SM_XLO;
    const unsigned WHIb = smem_base + SM_WHI, WLOb = smem_base + SM_WLO;

    const int tid = threadIdx.x;
    const int lane = tid & 31, w = tid >> 5;
    const long row0 = (long)blockIdx.x * 128;

    {
        const float4* x4 = (const float4*)x + row0 * 32;
#pragma unroll 4
        for (int i = 0; i < 16; ++i) {
            int e = i * 256 + tid;
            int r = e >> 5, f4c = e & 31;
            float4 v = x4[(long)r * 32 + f4c];
            int k = 4 * f4c;
            unsigned off = sw_off(r, k >> 3) + (unsigned)(k & 7) * 2u;
            u64 hi, lo;
            cvt_hi_lo(v, hi, lo);
            *(u64*)(smc + SM_XHI + off) = hi;
            *(u64*)(smc + SM_XLO + off) = lo;
        }
    }
    __syncthreads();

    const int a_row = (w << 4) + (lane & 15);
    const int a_cs  = lane >> 4;
    const int b_g   = lane & 7;
    const int b_cs  = (lane >> 3) & 1;

    for (int ch = 0; ch < 8; ++ch) {
        const int g0 = ch * 64;
        {
            const float4* sh = (const float4*)(g_whi + (size_t)ch * 16384);
            const float4* sl = (const float4*)(g_wlo + (size_t)ch * 16384);
            float4* dh = (float4*)(smc + SM_WHI);
            float4* dl = (float4*)(smc + SM_WLO);
#pragma unroll
            for (int i = 0; i < 4; ++i) {
                dh[i * 256 + tid] = sh[i * 256 + tid];
                dl[i * 256 + tid] = sl[i * 256 + tid];
            }
        }
        __syncthreads();

        float acc[8][4];
#pragma unroll
        for (int nt = 0; nt < 8; ++nt)
#pragma unroll
            for (int q = 0; q < 4; ++q) acc[nt][q] = 0.f;

#pragma unroll
        for (int ks = 0; ks < 8; ++ks) {
            unsigned aH[4], aL[4];
            ldmatrix_x4(aH, XHIb + sw_off(a_row, 2 * ks + a_cs));
            ldmatrix_x4(aL, XLOb + sw_off(a_row, 2 * ks + a_cs));
#pragma unroll
            for (int nt = 0; nt < 8; ++nt) {
                unsigned bH[2], bL[2];
                ldmatrix_x2(bH, WHIb + sw_off(nt * 8 + b_g, 2 * ks + b_cs));
                mma_bf16(acc[nt], aH, bH);
                mma_bf16(acc[nt], aL, bH);
                ldmatrix_x2(bL, WLOb + sw_off(nt * 8 + b_g, 2 * ks + b_cs));
                mma_bf16(acc[nt], aH, bL);
            }
        }

        {
            int r0 = (w << 4) + (lane >> 2);
            int c0 = (lane & 3) * 2;
#pragma unroll
            for (int nt = 0; nt < 8; ++nt) {
                int c = nt * 8 + c0;
                *(float2*)&STG[r0 * 68 + c]       = make_float2(acc[nt][0], acc[nt][1]);
                *(float2*)&STG[(r0 + 8) * 68 + c] = make_float2(acc[nt][2], acc[nt][3]);
            }
        }
        __syncthreads();

        {
            int cseg = tid & 15;
            int C = g0 + cseg * 4;
            float4 bi = __ldg((const float4*)bih + (C >> 2));
            float4 bh = __ldg((const float4*)bhh + (C >> 2));
            float4 bias = make_float4(bi.x + bh.x, bi.y + bh.y,
                                      bi.z + bh.z, bi.w + bh.w);
#pragma unroll
            for (int it = 0; it < 8; ++it) {
                int rr = (tid >> 4) + 16 * it;
                float4 v = *(const float4*)&STG[rr * 68 + cseg * 4];
                v.x += bias.x; v.y += bias.y; v.z += bias.z; v.w += bias.w;
                *(float4*)&g_xg[(row0 + rr) * 512 + C] = v;
            }
        }
        __syncthreads();
    }
}

// ---------------------------------------------------------------------------
// Kernel B: LSTM recurrence — R13 structure, RKQ=24/SKQ=8: weight LDS traffic
// halved (512 wf/step) at the cost of 96 weight registers per thread.
// ---------------------------------------------------------------------------
__global__ void __launch_bounds__(512, 1)
lstm_rec(const float* __restrict__ Whh, const float* __restrict__ Wo,
         const float* __restrict__ bo, float* __restrict__ out)
{
    extern __shared__ float sm[];
    float4* W4s = (float4*)sm;               // [32][128] (wi,wf,wg,wo) = 64 KB
    float* hbuf = sm + 32 * 128 * 4;         // [2][256] ping-pong (row*128+j)
    ulonglong2* part = (ulonglong2*)(hbuf + 512);  // [2][4][128] (aif,ago)

    const int th = threadIdx.x;
    const int j  = th & 127;
    const int kq = th >> 7;
    const int b0 = blockIdx.x * 2;
    const int k0 = 32 * kq;

    // smem weights: ks = q*SKQ + kk, k = 32q + RKQ + kk
    for (int e = th; e < 32 * 128; e += 512) {
        int jj = e & 127, ks = e >> 7;
        int q = ks >> 3, kk = ks & 7;
        int k = 32 * q + RKQ + kk;
        W4s[ks * 128 + jj] = make_float4(
            Whh[(0 * 128 + jj) * 128 + k], Whh[(1 * 128 + jj) * 128 + k],
            Whh[(2 * 128 + jj) * 128 + k], Whh[(3 * 128 + jj) * 128 + k]);
    }
    u64 wifr[RKQ], wgor[RKQ];
#pragma unroll
    for (int r = 0; r < RKQ; ++r) {
        int k = k0 + r;
        wifr[r] = pack2(Whh[(0 * 128 + j) * 128 + k], Whh[(1 * 128 + j) * 128 + k]);
        wgor[r] = pack2(Whh[(2 * 128 + j) * 128 + k], Whh[(3 * 128 + j) * 128 + k]);
    }

    hbuf[th] = 0.f;
    float c = 0.f;

    const float* xgp = g_xg + (long)(b0 + (kq & 1)) * T_SEQ * 512;
    float p0 = 0.f, p1 = 0.f, p2 = 0.f, p3 = 0.f;
    if (kq < 2) {
        p0 = __ldg(xgp + j);       p1 = __ldg(xgp + 128 + j);
        p2 = __ldg(xgp + 256 + j); p3 = __ldg(xgp + 384 + j);
    }

    __syncthreads();

    for (int step = 0; step < T_SEQ; ++step) {
        const float* hc = hbuf + ((step & 1) << 8);
        float* hn = hbuf + (((step + 1) & 1) << 8);

        const float4* hA4 = (const float4*)(hc + k0);
        const float4* hB4 = (const float4*)(hc + 128 + k0);

        u64 aif0 = 0ull, ago0 = 0ull, aif1 = 0ull, ago1 = 0ull;

        // register k's: 6 float4 chunks (24 k)
#pragma unroll
        for (int q = 0; q < RKQ / 4; ++q) {
            float4 H0 = hA4[q], H1 = hB4[q];
#pragma unroll
            for (int cc = 0; cc < 4; ++cc) {
                int r = 4 * q + cc;
                float hx0 = (cc == 0) ? H0.x : (cc == 1) ? H0.y : (cc == 2) ? H0.z : H0.w;
                float hx1 = (cc == 0) ? H1.x : (cc == 1) ? H1.y : (cc == 2) ? H1.z : H1.w;
                u64 d0 = dup2(hx0), d1 = dup2(hx1);
                ffma2(aif0, wifr[r], d0); ffma2(ago0, wgor[r], d0);
                ffma2(aif1, wifr[r], d1); ffma2(ago1, wgor[r], d1);
            }
        }
        // smem k's: 2 float4 chunks (8 k), weights via LDS.128
#pragma unroll
        for (int q = 0; q < SKQ / 4; ++q) {
            float4 H0 = hA4[RKQ / 4 + q], H1 = hB4[RKQ / 4 + q];
            const float4* wp = W4s + (kq * SKQ + 4 * q) * 128 + j;
#pragma unroll
            for (int cc = 0; cc < 4; ++cc) {
                float4 wv = wp[cc * 128];
                u64 wif = pack2(wv.x, wv.y);
                u64 wgo = pack2(wv.z, wv.w);
                float hx0 = (cc == 0) ? H0.x : (cc == 1) ? H0.y : (cc == 2) ? H0.z : H0.w;
                float hx1 = (cc == 0) ? H1.x : (cc == 1) ? H1.y : (cc == 2) ? H1.z : H1.w;
                u64 d0 = dup2(hx0), d1 = dup2(hx1);
                ffma2(aif0, wif, d0); ffma2(ago0, wgo, d0);
                ffma2(aif1, wif, d1); ffma2(ago1, wgo, d1);
            }
        }

        if (kq == 0) {
            part[(1 << 9) + (0 << 7) + j] = make_ulonglong2(aif1, ago1);
        } else if (kq == 1) {
            part[(0 << 9) + (1 << 7) + j] = make_ulonglong2(aif0, ago0);
        } else {
            part[(0 << 9) + (kq << 7) + j] = make_ulonglong2(aif0, ago0);
            part[(1 << 9) + (kq << 7) + j] = make_ulonglong2(aif1, ago1);
        }
        __syncthreads();

        if (kq < 2) {
            u64 aif = (kq == 0) ? aif0 : aif1;
            u64 ago = (kq == 0) ? ago0 : ago1;
#pragma unroll
            for (int qq = 1; qq < 4; ++qq) {
                int src = (kq + qq) & 3;
                ulonglong2 v = part[(kq << 9) + (src << 7) + j];
                aif = add2(aif, v.x);
                ago = add2(ago, v.y);
            }
            aif = add2(aif, pack2(p0, p1));
            ago = add2(ago, pack2(p2, p3));

            int ns = (step + 1 < T_SEQ) ? step + 1 : step;
            const float* qp = xgp + (long)ns * 512 + j;
            p0 = __ldg(qp); p1 = __ldg(qp + 128); p2 = __ldg(qp + 256); p3 = __ldg(qp + 384);

            float ai, af, ag, ao;
            unpack2(aif, ai, af); unpack2(ago, ag, ao);
            float iv = sigapx(ai), fv = sigapx(af), gv = tanhapx(ag), ov = sigapx(ao);
            c = fv * c + iv * gv;
            float nh = ov * tanhapx(c);
            hn[(kq << 7) + j] = nh;
        }
        __syncthreads();
    }

    // Output projection (final h in buffer 0 since T_SEQ is even)
    if (th < 128) {
        int t = th;
        float acc0 = bo[t], acc1 = acc0;
        const float4* wo4 = (const float4*)(Wo + t * 128);
        const float4* h04 = (const float4*)hbuf;
        const float4* h14 = (const float4*)(hbuf + 128);
#pragma unroll
        for (int k4 = 0; k4 < 32; ++k4) {
            float4 wv = wo4[k4];
            float4 a = h04[k4];
            float4 b = h14[k4];
            acc0 += wv.x * a.x + wv.y * a.y + wv.z * a.z + wv.w * a.w;
            acc1 += wv.x * b.x + wv.y * b.y + wv.z * b.z + wv.w * b.w;
        }
        out[b0 * 128 + t] = acc0;
        out[(b0 + 1) * 128 + t] = acc1;
    }
}

// ---------------------------------------------------------------------------

extern "C" void kernel_launch(void* const* d_in, const int* in_sizes, int n_in,
                              void* d_out, int out_size)
{
    const float* x   = (const float*)d_in[0];
    const float* Wih = (const float*)d_in[1];
    const float* Whh = (const float*)d_in[2];
    const float* bih = (const float*)d_in[3];
    const float* bhh = (const float*)d_in[4];
    const float* Wo  = (const float*)d_in[5];
    const float* bo  = (const float*)d_in[6];
    float* out = (float*)d_out;

    // lstm_rec smem: W4s 65536 + hbuf 2048 + part 16384 = 83968 B
    const int smB = 65536 + 2048 + 16384;
    cudaFuncSetAttribute(xg_mma, cudaFuncAttributeMaxDynamicSharedMemorySize, SM_TOTAL_A);
    cudaFuncSetAttribute(lstm_rec, cudaFuncAttributeMaxDynamicSharedMemorySize, smB);

    wprep<<<64, 256>>>(Wih);
    xg_mma<<<4096, 256, SM_TOTAL_A>>>(x, Wih, bih, bhh);
    lstm_rec<<<128, 512, smB>>>(Whh, Wo, bo, out);
}

// round 17
// speedup vs baseline: 1.0721x; 1.0721x over previous
#include <cuda_runtime.h>
#include <cuda_bf16.h>
#include <math.h>

#define T_SEQ 2048
#define BATCH 256
// lstm_rec per k-quarter (32 k): RKQ in registers, SKQ in smem (champion config)
#define RKQ 16
#define SKQ 16

typedef unsigned long long u64;

// xg scratch: [B][T][4H] fp32 = 1 GiB. __device__ global (no cudaMalloc allowed).
__device__ float g_xg[268435456];
// Pre-converted Wih bf16 hi/lo, per-chunk swizzled images (8 chunks x 16 KB).
__device__ __align__(16) unsigned char g_whi[131072];
__device__ __align__(16) unsigned char g_wlo[131072];

// ---- f32x2 packed-math helpers (sm_103a FFMA2) --------------------------
__device__ __forceinline__ u64 pack2(float lo, float hi) {
    u64 r; asm("mov.b64 %0, {%1, %2};" : "=l"(r) : "f"(lo), "f"(hi)); return r;
}
__device__ __forceinline__ u64 dup2(float v) {
    u64 r; asm("mov.b64 %0, {%1, %1};" : "=l"(r) : "f"(v)); return r;
}
__device__ __forceinline__ void ffma2(u64& d, u64 a, u64 b) {
    asm("fma.rn.f32x2 %0, %1, %2, %0;" : "+l"(d) : "l"(a), "l"(b));
}
__device__ __forceinline__ u64 add2(u64 a, u64 b) {
    u64 r; asm("add.rn.f32x2 %0, %1, %2;" : "=l"(r) : "l"(a), "l"(b)); return r;
}
__device__ __forceinline__ void unpack2(u64 v, float& lo, float& hi) {
    asm("mov.b64 {%0, %1}, %2;" : "=f"(lo), "=f"(hi) : "l"(v));
}
__device__ __forceinline__ float tanhapx(float x) {
    float r; asm("tanh.approx.f32 %0, %1;" : "=f"(r) : "f"(x)); return r;
}
__device__ __forceinline__ float sigapx(float x) {
    return fmaf(0.5f, tanhapx(0.5f * x), 0.5f);
}

// ---- shared helpers -------------------------------------------------------
__device__ __forceinline__ unsigned smem_u32(const void* p) {
    unsigned a;
    asm("{ .reg .u64 t; cvta.to.shared.u64 t, %1; cvt.u32.u64 %0, t; }"
        : "=r"(a) : "l"(p));
    return a;
}
__device__ __forceinline__ void ldmatrix_x4(unsigned* r, unsigned addr) {
    asm volatile("ldmatrix.sync.aligned.m8n8.x4.shared.b16 {%0,%1,%2,%3}, [%4];"
                 : "=r"(r[0]), "=r"(r[1]), "=r"(r[2]), "=r"(r[3]) : "r"(addr));
}
__device__ __forceinline__ void ldmatrix_x2(unsigned* r, unsigned addr) {
    asm volatile("ldmatrix.sync.aligned.m8n8.x2.shared.b16 {%0,%1}, [%2];"
                 : "=r"(r[0]), "=r"(r[1]) : "r"(addr));
}
__device__ __forceinline__ void mma_bf16(float* d, const unsigned* a, const unsigned* b) {
    asm volatile(
        "mma.sync.aligned.m16n8k16.row.col.f32.bf16.bf16.f32 "
        "{%0,%1,%2,%3}, {%4,%5,%6,%7}, {%8,%9}, {%0,%1,%2,%3};"
        : "+f"(d[0]), "+f"(d[1]), "+f"(d[2]), "+f"(d[3])
        : "r"(a[0]), "r"(a[1]), "r"(a[2]), "r"(a[3]), "r"(b[0]), "r"(b[1]));
}
__device__ __forceinline__ unsigned short bfbits(__nv_bfloat16 h) {
    unsigned short s; memcpy(&s, &h, 2); return s;
}
// swizzled byte offset of 16B chunk c in row r (rows of 256B = 128 bf16)
__device__ __forceinline__ unsigned sw_off(int r, int c) {
    return (unsigned)r * 256u + (unsigned)(c ^ (r & 7)) * 16u;
}
__device__ __forceinline__ void cvt_hi_lo(float4 v, u64& hi, u64& lo) {
    __nv_bfloat16 hx = __float2bfloat16_rn(v.x);
    __nv_bfloat16 hy = __float2bfloat16_rn(v.y);
    __nv_bfloat16 hz = __float2bfloat16_rn(v.z);
    __nv_bfloat16 hw = __float2bfloat16_rn(v.w);
    hi = (u64)bfbits(hx) | ((u64)bfbits(hy) << 16)
       | ((u64)bfbits(hz) << 32) | ((u64)bfbits(hw) << 48);
    __nv_bfloat16 lx = __float2bfloat16_rn(v.x - __bfloat162float(hx));
    __nv_bfloat16 ly = __float2bfloat16_rn(v.y - __bfloat162float(hy));
    __nv_bfloat16 lz = __float2bfloat16_rn(v.z - __bfloat162float(hz));
    __nv_bfloat16 lw = __float2bfloat16_rn(v.w - __bfloat162float(hw));
    lo = (u64)bfbits(lx) | ((u64)bfbits(ly) << 16)
       | ((u64)bfbits(lz) << 32) | ((u64)bfbits(lw) << 48);
}

// ============================================================================
// Kernel W: one-shot Wih -> bf16 hi/lo in per-chunk swizzled blocked layout.
// ============================================================================
__global__ void __launch_bounds__(256, 4)
wprep(const float* __restrict__ Wih)
{
    int e = blockIdx.x * 256 + threadIdx.x;   // 0..16383
    int ch = e >> 11;
    int r  = (e >> 5) & 63;
    int f4c = e & 31;
    int g = ch * 64 + r;
    float4 v = ((const float4*)Wih)[g * 32 + f4c];
    int k = 4 * f4c;
    unsigned off = (unsigned)(ch * 16384) + sw_off(r, k >> 3) + (unsigned)(k & 7) * 2u;
    u64 hi, lo;
    cvt_hi_lo(v, hi, lo);
    *(u64*)(g_whi + off) = hi;
    *(u64*)(g_wlo + off) = lo;
}

// ============================================================================
// Kernel A: xg = x @ Wih^T + bih + bhh via mma.sync bf16-3x.
// Pre-converted W chunks copied from global; fused single ks-loop reusing
// a/b fragments across the 3 precision passes (hi.hi + lo.hi + hi.lo).
// ============================================================================

#define SM_XHI 0
#define SM_XLO 32768
#define SM_WHI 65536
#define SM_WLO 81920
#define SM_STAGE 98304            // [128][68] f32 = 34816 B
#define SM_TOTAL_A 133120

__global__ void __launch_bounds__(256, 1)
xg_mma(const float* __restrict__ x, const float* __restrict__ Wih,
       const float* __restrict__ bih, const float* __restrict__ bhh)
{
    extern __shared__ char smc[];
    float* STG = (float*)(smc + SM_STAGE);
    const unsigned smem_base = smem_u32(smc);
    const unsigned XHIb = smem_base + SM_XHI, XLOb = smem_base + SM_XLO;
    const unsigned WHIb = smem_base + SM_WHI, WLOb = smem_base + SM_WLO;

    const int tid = threadIdx.x;
    const int lane = tid & 31, w = tid >> 5;
    const long row0 = (long)blockIdx.x * 128;

    {
        const float4* x4 = (const float4*)x + row0 * 32;
#pragma unroll 4
        for (int i = 0; i < 16; ++i) {
            int e = i * 256 + tid;
            int r = e >> 5, f4c = e & 31;
            float4 v = x4[(long)r * 32 + f4c];
            int k = 4 * f4c;
            unsigned off = sw_off(r, k >> 3) + (unsigned)(k & 7) * 2u;
            u64 hi, lo;
            cvt_hi_lo(v, hi, lo);
            *(u64*)(smc + SM_XHI + off) = hi;
            *(u64*)(smc + SM_XLO + off) = lo;
        }
    }
    __syncthreads();

    const int a_row = (w << 4) + (lane & 15);
    const int a_cs  = lane >> 4;
    const int b_g   = lane & 7;
    const int b_cs  = (lane >> 3) & 1;

    for (int ch = 0; ch < 8; ++ch) {
        const int g0 = ch * 64;
        {
            const float4* sh = (const float4*)(g_whi + (size_t)ch * 16384);
            const float4* sl = (const float4*)(g_wlo + (size_t)ch * 16384);
            float4* dh = (float4*)(smc + SM_WHI);
            float4* dl = (float4*)(smc + SM_WLO);
#pragma unroll
            for (int i = 0; i < 4; ++i) {
                dh[i * 256 + tid] = sh[i * 256 + tid];
                dl[i * 256 + tid] = sl[i * 256 + tid];
            }
        }
        __syncthreads();

        float acc[8][4];
#pragma unroll
        for (int nt = 0; nt < 8; ++nt)
#pragma unroll
            for (int q = 0; q < 4; ++q) acc[nt][q] = 0.f;

#pragma unroll
        for (int ks = 0; ks < 8; ++ks) {
            unsigned aH[4], aL[4];
            ldmatrix_x4(aH, XHIb + sw_off(a_row, 2 * ks + a_cs));
            ldmatrix_x4(aL, XLOb + sw_off(a_row, 2 * ks + a_cs));
#pragma unroll
            for (int nt = 0; nt < 8; ++nt) {
                unsigned bH[2], bL[2];
                ldmatrix_x2(bH, WHIb + sw_off(nt * 8 + b_g, 2 * ks + b_cs));
                mma_bf16(acc[nt], aH, bH);      // hi . hi
                mma_bf16(acc[nt], aL, bH);      // lo . hi
                ldmatrix_x2(bL, WLOb + sw_off(nt * 8 + b_g, 2 * ks + b_cs));
                mma_bf16(acc[nt], aH, bL);      // hi . lo
            }
        }

        {
            int r0 = (w << 4) + (lane >> 2);
            int c0 = (lane & 3) * 2;
#pragma unroll
            for (int nt = 0; nt < 8; ++nt) {
                int c = nt * 8 + c0;
                *(float2*)&STG[r0 * 68 + c]       = make_float2(acc[nt][0], acc[nt][1]);
                *(float2*)&STG[(r0 + 8) * 68 + c] = make_float2(acc[nt][2], acc[nt][3]);
            }
        }
        __syncthreads();

        {
            int cseg = tid & 15;
            int C = g0 + cseg * 4;
            float4 bi = __ldg((const float4*)bih + (C >> 2));
            float4 bh = __ldg((const float4*)bhh + (C >> 2));
            float4 bias = make_float4(bi.x + bh.x, bi.y + bh.y,
                                      bi.z + bh.z, bi.w + bh.w);
#pragma unroll
            for (int it = 0; it < 8; ++it) {
                int rr = (tid >> 4) + 16 * it;
                float4 v = *(const float4*)&STG[rr * 68 + cseg * 4];
                v.x += bias.x; v.y += bias.y; v.z += bias.z; v.w += bias.w;
                *(float4*)&g_xg[(row0 + rr) * 512 + C] = v;
            }
        }
        __syncthreads();
    }
}

// ---------------------------------------------------------------------------
// Kernel B: LSTM recurrence — champion config (R13/R15). Thread (j, kq):
// j = th&127, kq = th>>7 owns 32 k's. RKQ=16 in regs, SKQ=16 from smem as
// interleaved float4. Partial exchange via smem; kq<2 finalize row=kq with
// HW tanh. 2 barriers/step.
// ---------------------------------------------------------------------------
__global__ void __launch_bounds__(512, 1)
lstm_rec(const float* __restrict__ Whh, const float* __restrict__ Wo,
         const float* __restrict__ bo, float* __restrict__ out)
{
    extern __shared__ float sm[];
    float4* W4s = (float4*)sm;               // [64][128] (wi,wf,wg,wo) = 128 KB
    float* hbuf = sm + 64 * 128 * 4;         // [2][256] ping-pong (row*128+j)
    ulonglong2* part = (ulonglong2*)(hbuf + 512);  // [2][4][128] (aif,ago)

    const int th = threadIdx.x;
    const int j  = th & 127;
    const int kq = th >> 7;
    const int b0 = blockIdx.x * 2;
    const int k0 = 32 * kq;

    for (int e = th; e < 64 * 128; e += 512) {
        int jj = e & 127, ks = e >> 7;
        int q = ks >> 4, kk = ks & 15;
        int k = 32 * q + RKQ + kk;
        W4s[ks * 128 + jj] = make_float4(
            Whh[(0 * 128 + jj) * 128 + k], Whh[(1 * 128 + jj) * 128 + k],
            Whh[(2 * 128 + jj) * 128 + k], Whh[(3 * 128 + jj) * 128 + k]);
    }
    u64 wifr[RKQ], wgor[RKQ];
#pragma unroll
    for (int r = 0; r < RKQ; ++r) {
        int k = k0 + r;
        wifr[r] = pack2(Whh[(0 * 128 + j) * 128 + k], Whh[(1 * 128 + j) * 128 + k]);
        wgor[r] = pack2(Whh[(2 * 128 + j) * 128 + k], Whh[(3 * 128 + j) * 128 + k]);
    }

    hbuf[th] = 0.f;
    float c = 0.f;

    const float* xgp = g_xg + (long)(b0 + (kq & 1)) * T_SEQ * 512;
    float p0 = 0.f, p1 = 0.f, p2 = 0.f, p3 = 0.f;
    if (kq < 2) {
        p0 = __ldg(xgp + j);       p1 = __ldg(xgp + 128 + j);
        p2 = __ldg(xgp + 256 + j); p3 = __ldg(xgp + 384 + j);
    }

    __syncthreads();

    for (int step = 0; step < T_SEQ; ++step) {
        const float* hc = hbuf + ((step & 1) << 8);
        float* hn = hbuf + (((step + 1) & 1) << 8);

        const float4* hA4 = (const float4*)(hc + k0);
        const float4* hB4 = (const float4*)(hc + 128 + k0);

        u64 aif0 = 0ull, ago0 = 0ull, aif1 = 0ull, ago1 = 0ull;

        // register k's: 4 float4 chunks (16 k)
#pragma unroll
        for (int q = 0; q < RKQ / 4; ++q) {
            float4 H0 = hA4[q], H1 = hB4[q];
#pragma unroll
            for (int cc = 0; cc < 4; ++cc) {
                int r = 4 * q + cc;
                float hx0 = (cc == 0) ? H0.x : (cc == 1) ? H0.y : (cc == 2) ? H0.z : H0.w;
                float hx1 = (cc == 0) ? H1.x : (cc == 1) ? H1.y : (cc == 2) ? H1.z : H1.w;
                u64 d0 = dup2(hx0), d1 = dup2(hx1);
                ffma2(aif0, wifr[r], d0); ffma2(ago0, wgor[r], d0);
                ffma2(aif1, wifr[r], d1); ffma2(ago1, wgor[r], d1);
            }
        }
        // smem k's: 4 float4 chunks (16 k), weights via LDS.128
#pragma unroll
        for (int q = 0; q < SKQ / 4; ++q) {
            float4 H0 = hA4[RKQ / 4 + q], H1 = hB4[RKQ / 4 + q];
            const float4* wp = W4s + (kq * SKQ + 4 * q) * 128 + j;
#pragma unroll
            for (int cc = 0; cc < 4; ++cc) {
                float4 wv = wp[cc * 128];
                u64 wif = pack2(wv.x, wv.y);
                u64 wgo = pack2(wv.z, wv.w);
                float hx0 = (cc == 0) ? H0.x : (cc == 1) ? H0.y : (cc == 2) ? H0.z : H0.w;
                float hx1 = (cc == 0) ? H1.x : (cc == 1) ? H1.y : (cc == 2) ? H1.z : H1.w;
                u64 d0 = dup2(hx0), d1 = dup2(hx1);
                ffma2(aif0, wif, d0); ffma2(ago0, wgo, d0);
                ffma2(aif1, wif, d1); ffma2(ago1, wgo, d1);
            }
        }

        if (kq == 0) {
            part[(1 << 9) + (0 << 7) + j] = make_ulonglong2(aif1, ago1);
        } else if (kq == 1) {
            part[(0 << 9) + (1 << 7) + j] = make_ulonglong2(aif0, ago0);
        } else {
            part[(0 << 9) + (kq << 7) + j] = make_ulonglong2(aif0, ago0);
            part[(1 << 9) + (kq << 7) + j] = make_ulonglong2(aif1, ago1);
        }
        __syncthreads();

        if (kq < 2) {
            u64 aif = (kq == 0) ? aif0 : aif1;
            u64 ago = (kq == 0) ? ago0 : ago1;
#pragma unroll
            for (int qq = 1; qq < 4; ++qq) {
                int src = (kq + qq) & 3;
                ulonglong2 v = part[(kq << 9) + (src << 7) + j];
                aif = add2(aif, v.x);
                ago = add2(ago, v.y);
            }
            aif = add2(aif, pack2(p0, p1));
            ago = add2(ago, pack2(p2, p3));

            int ns = (step + 1 < T_SEQ) ? step + 1 : step;
            const float* qp = xgp + (long)ns * 512 + j;
            p0 = __ldg(qp); p1 = __ldg(qp + 128); p2 = __ldg(qp + 256); p3 = __ldg(qp + 384);

            float ai, af, ag, ao;
            unpack2(aif, ai, af); unpack2(ago, ag, ao);
            float iv = sigapx(ai), fv = sigapx(af), gv = tanhapx(ag), ov = sigapx(ao);
            c = fv * c + iv * gv;
            float nh = ov * tanhapx(c);
            hn[(kq << 7) + j] = nh;
        }
        __syncthreads();
    }

    // Output projection (final h in buffer 0 since T_SEQ is even)
    if (th < 128) {
        int t = th;
        float acc0 = bo[t], acc1 = acc0;
        const float4* wo4 = (const float4*)(Wo + t * 128);
        const float4* h04 = (const float4*)hbuf;
        const float4* h14 = (const float4*)(hbuf + 128);
#pragma unroll
        for (int k4 = 0; k4 < 32; ++k4) {
            float4 wv = wo4[k4];
            float4 a = h04[k4];
            float4 b = h14[k4];
            acc0 += wv.x * a.x + wv.y * a.y + wv.z * a.z + wv.w * a.w;
            acc1 += wv.x * b.x + wv.y * b.y + wv.z * b.z + wv.w * b.w;
        }
        out[b0 * 128 + t] = acc0;
        out[(b0 + 1) * 128 + t] = acc1;
    }
}

// ---------------------------------------------------------------------------

extern "C" void kernel_launch(void* const* d_in, const int* in_sizes, int n_in,
                              void* d_out, int out_size)
{
    const float* x   = (const float*)d_in[0];
    const float* Wih = (const float*)d_in[1];
    const float* Whh = (const float*)d_in[2];
    const float* bih = (const float*)d_in[3];
    const float* bhh = (const float*)d_in[4];
    const float* Wo  = (const float*)d_in[5];
    const float* bo  = (const float*)d_in[6];
    float* out = (float*)d_out;

    // lstm_rec smem: W4s 131072 + hbuf 2048 + part 16384 = 149504 B
    const int smB = 131072 + 2048 + 16384;
    cudaFuncSetAttribute(xg_mma, cudaFuncAttributeMaxDynamicSharedMemorySize, SM_TOTAL_A);
    cudaFuncSetAttribute(lstm_rec, cudaFuncAttributeMaxDynamicSharedMemorySize, smB);

    wprep<<<64, 256>>>(Wih);
    xg_mma<<<4096, 256, SM_TOTAL_A>>>(x, Wih, bih, bhh);
    lstm_rec<<<128, 512, smB>>>(Whh, Wo, bo, out);
}